// round 5
// baseline (speedup 1.0000x reference)
#include <cuda_runtime.h>

// ConvQuadInterp3d over x:(2,1,8,512,512) fp32.
// Output = coords_max (B,1,3,D,H,W) then y_max (B,1,D,H,W), fp32.
// One thread per (b,h,w); fully-unrolled d loop; rolling window where the
// previous plane keeps only its 5 cross values + column maxima (corners are
// NMS-only and covered by colmax); 9 precomputed clamped neighbor pointers so
// all loads are [ptr + const] with zero per-iteration address math.

#define Dd 8
#define Hh 512
#define Ww 512
#define Bb 2
#define PLANE (Hh * Ww)

#define LOADP(dn, P, cm) do {                                                   \
    P[0] = __ldg(r00 + (dn) * PLANE); P[1] = __ldg(r01 + (dn) * PLANE);         \
    P[2] = __ldg(r02 + (dn) * PLANE); P[3] = __ldg(r10 + (dn) * PLANE);         \
    P[4] = __ldg(r11 + (dn) * PLANE); P[5] = __ldg(r12 + (dn) * PLANE);         \
    P[6] = __ldg(r20 + (dn) * PLANE); P[7] = __ldg(r21 + (dn) * PLANE);         \
    P[8] = __ldg(r22 + (dn) * PLANE);                                           \
    cm[0] = fmaxf(P[0], fmaxf(P[3], P[6]));                                     \
    cm[1] = fmaxf(P[1], fmaxf(P[4], P[7]));                                     \
    cm[2] = fmaxf(P[2], fmaxf(P[5], P[8]));                                     \
} while (0)

__global__ void __launch_bounds__(128, 8)
conv_quad_interp3d_kernel(const float* __restrict__ x, float* __restrict__ out) {
    const int w = blockIdx.x * 32 + threadIdx.x;
    const int h = blockIdx.y * 4 + threadIdx.y;
    const int b = blockIdx.z;

    const int wm = max(w - 1, 0), wp = min(w + 1, Ww - 1);
    const int hm = max(h - 1, 0), hp = min(h + 1, Hh - 1);
    const float wf = (float)w, hf = (float)h;

    // 9 clamped neighbor pointers into plane 0; plane d adds a compile-time
    // immediate (d * PLANE * 4 bytes) inside the unrolled loop.
    const float* base = x + b * Dd * PLANE;
    const float* r00 = base + hm * Ww + wm;
    const float* r01 = base + hm * Ww + w;
    const float* r02 = base + hm * Ww + wp;
    const float* r10 = base + h  * Ww + wm;
    const float* r11 = base + h  * Ww + w;
    const float* r12 = base + h  * Ww + wp;
    const float* r20 = base + hp * Ww + wm;
    const float* r21 = base + hp * Ww + w;
    const float* r22 = base + hp * Ww + wp;

    // Window state: prev plane keeps only cross values + colmax.
    float pm1, pm3, pm4, pm5, pm7, cp0, cp1, cp2;
    float C[9], cmc[3], N[9], cmn[3];

    LOADP(0, C, cmc);
    pm1 = C[1]; pm3 = C[3]; pm4 = C[4]; pm5 = C[5]; pm7 = C[7];  // replicate d=-1
    cp0 = cmc[0]; cp1 = cmc[1]; cp2 = cmc[2];
    LOADP(1, N, cmn);

    const int hw = h * Ww + w;
    float* pD = out + (b * 3 + 0) * Dd * PLANE + hw;
    float* pW = out + (b * 3 + 1) * Dd * PLANE + hw;
    float* pH = out + (b * 3 + 2) * Dd * PLANE + hw;
    float* pY = out + (Bb * 3) * Dd * PLANE + b * Dd * PLANE + hw;

#pragma unroll
    for (int d = 0; d < Dd; d++) {
        const float c = C[4];

        // Separable NMS over the 9 cached column maxima.
        float m = fmaxf(cp0, fmaxf(cp1, cp2));
        m = fmaxf(m, fmaxf(cmc[0], fmaxf(cmc[1], cmc[2])));
        m = fmaxf(m, fmaxf(cmn[0], fmaxf(cmn[1], cmn[2])));
        const bool nms = (c == m);

        // Gradients (central diff / 2, replicate pad)
        const float gx = 0.5f * (C[5] - C[3]);
        const float gy = 0.5f * (C[7] - C[1]);
        const float gs = 0.5f * (N[4] - pm4);

        // Hessian (cross terms * 0.25 per reference)
        const float axx = C[3] + C[5] - 2.0f * c;
        const float ayy = C[1] + C[7] - 2.0f * c;
        const float ass = pm4 + N[4] - 2.0f * c;
        const float axy = 0.25f * (C[0] + C[8] - C[6] - C[2]);
        const float ays = 0.25f * (pm1 + N[7] - N[1] - pm7);
        const float axs = 0.25f * (pm3 + N[5] - N[3] - pm5);

        // Symmetric 3x3 solve via adjugate (Cramer)
        const float c00 = ayy * ass - ays * ays;
        const float c01 = axs * ays - axy * ass;
        const float c02 = axy * ays - axs * ayy;
        const float det = axx * c00 + axy * c01 + axs * c02;
        const bool keep = nms && (det != 0.0f);

        float rx = 0.0f, ry = 0.0f, rs = 0.0f;
        if (keep) {
            const float inv = 1.0f / det;
            const float c11 = axx * ass - axs * axs;
            const float c12 = axy * axs - axx * ays;
            const float c22 = axx * ayy - axy * axy;
            rx = -(c00 * gx + c01 * gy + c02 * gs) * inv;
            ry = -(c01 * gx + c11 * gy + c12 * gs) * inv;
            rs = -(c02 * gx + c12 * gy + c22 * gs) * inv;
            const float big = fmaxf(fabsf(rx), fmaxf(fabsf(ry), fabsf(rs)));
            if (big > 0.7f) { rx = 0.0f; ry = 0.0f; rs = 0.0f; }
        }

        const float dyv = 0.5f * (gx * rx + gy * ry + gs * rs);
        const float y = c + dyv + (keep ? 10.0f : 0.0f);

        // coords channels: grid(d, w, h) + flipped refinement (s, y, x)
        pD[d * PLANE] = (float)d + rs;
        pW[d * PLANE] = wf + ry;
        pH[d * PLANE] = hf + rx;
        pY[d * PLANE] = y;

        if (d < Dd - 1) {
            pm1 = C[1]; pm3 = C[3]; pm4 = C[4]; pm5 = C[5]; pm7 = C[7];
            cp0 = cmc[0]; cp1 = cmc[1]; cp2 = cmc[2];
#pragma unroll
            for (int i = 0; i < 9; i++) C[i] = N[i];
#pragma unroll
            for (int i = 0; i < 3; i++) cmc[i] = cmn[i];
            const int dn = (d + 2 < Dd) ? d + 2 : Dd - 1;
            LOADP(dn, N, cmn);
        }
    }
}

extern "C" void kernel_launch(void* const* d_in, const int* in_sizes, int n_in,
                              void* d_out, int out_size) {
    const float* x = (const float*)d_in[0];
    float* out = (float*)d_out;
    dim3 block(32, 4, 1);
    dim3 grid(Ww / 32, Hh / 4, Bb);  // (16, 128, 2)
    conv_quad_interp3d_kernel<<<grid, block>>>(x, out);
}

// round 6
// speedup vs baseline: 1.5172x; 1.5172x over previous
#include <cuda_runtime.h>

// ConvQuadInterp3d over x:(2,1,8,512,512) fp32.
// Output = coords_max (B,1,3,D,H,W) then y_max (B,1,D,H,W), fp32.
// One thread per (b,h,w); fully-unrolled d loop; depth-2 software pipeline:
// window = prev-cross + C(plane d) + N(plane d+1), with Q = plane d+2 already
// in flight (issued one full iteration before consumption) to hide L2 latency.

#define Dd 8
#define Hh 512
#define Ww 512
#define Bb 2
#define PLANE (Hh * Ww)

__global__ void __launch_bounds__(128, 6)
conv_quad_interp3d_kernel(const float* __restrict__ x, float* __restrict__ out) {
    const int w = blockIdx.x * 32 + threadIdx.x;
    const int h = blockIdx.y * 4 + threadIdx.y;
    const int b = blockIdx.z;

    const int wm = max(w - 1, 0), wp = min(w + 1, Ww - 1);
    const int hm = max(h - 1, 0), hp = min(h + 1, Hh - 1);
    const float wf = (float)w, hf = (float)h;

    const float* xb = x + b * Dd * PLANE;
    // Nine 32-bit element offsets off one 64-bit base.
    const int o00 = hm * Ww + wm, o01 = hm * Ww + w, o02 = hm * Ww + wp;
    const int o10 = h  * Ww + wm, o11 = h  * Ww + w, o12 = h  * Ww + wp;
    const int o20 = hp * Ww + wm, o21 = hp * Ww + w, o22 = hp * Ww + wp;

#define LOADQ(dn, P) do { const float* p_ = xb + (dn) * PLANE;                  \
    P[0] = __ldg(p_ + o00); P[1] = __ldg(p_ + o01); P[2] = __ldg(p_ + o02);     \
    P[3] = __ldg(p_ + o10); P[4] = __ldg(p_ + o11); P[5] = __ldg(p_ + o12);     \
    P[6] = __ldg(p_ + o20); P[7] = __ldg(p_ + o21); P[8] = __ldg(p_ + o22);     \
} while (0)

#define COLMAX(P, cm) do {                                                      \
    cm[0] = fmaxf(P[0], fmaxf(P[3], P[6]));                                     \
    cm[1] = fmaxf(P[1], fmaxf(P[4], P[7]));                                     \
    cm[2] = fmaxf(P[2], fmaxf(P[5], P[8]));                                     \
} while (0)

    float C[9], N[9], Q[9], cmc[3], cmn[3];
    float pm1, pm3, pm4, pm5, pm7, cp0, cp1, cp2;

    LOADQ(0, C); COLMAX(C, cmc);
    pm1 = C[1]; pm3 = C[3]; pm4 = C[4]; pm5 = C[5]; pm7 = C[7];  // replicate d=-1
    cp0 = cmc[0]; cp1 = cmc[1]; cp2 = cmc[2];
    LOADQ(1, N); COLMAX(N, cmn);
    LOADQ(2, Q);                                    // in flight across iter 0

    const int hw = h * Ww + w;
    float* pD = out + (b * 3 + 0) * Dd * PLANE + hw;
    float* pW = out + (b * 3 + 1) * Dd * PLANE + hw;
    float* pH = out + (b * 3 + 2) * Dd * PLANE + hw;
    float* pY = out + (Bb * 3) * Dd * PLANE + b * Dd * PLANE + hw;

#pragma unroll
    for (int d = 0; d < Dd; d++) {
        const float c = C[4];

        // Separable NMS over cached column maxima of planes d-1, d, d+1.
        float m = fmaxf(cp0, fmaxf(cp1, cp2));
        m = fmaxf(m, fmaxf(cmc[0], fmaxf(cmc[1], cmc[2])));
        m = fmaxf(m, fmaxf(cmn[0], fmaxf(cmn[1], cmn[2])));
        const bool nms = (c == m);

        // Gradients (central diff / 2, replicate pad)
        const float gx = 0.5f * (C[5] - C[3]);
        const float gy = 0.5f * (C[7] - C[1]);
        const float gs = 0.5f * (N[4] - pm4);

        // Hessian (cross terms * 0.25 per reference)
        const float axx = C[3] + C[5] - 2.0f * c;
        const float ayy = C[1] + C[7] - 2.0f * c;
        const float ass = pm4 + N[4] - 2.0f * c;
        const float axy = 0.25f * (C[0] + C[8] - C[6] - C[2]);
        const float ays = 0.25f * (pm1 + N[7] - N[1] - pm7);
        const float axs = 0.25f * (pm3 + N[5] - N[3] - pm5);

        // Symmetric 3x3 solve via adjugate (Cramer)
        const float c00 = ayy * ass - ays * ays;
        const float c01 = axs * ays - axy * ass;
        const float c02 = axy * ays - axs * ayy;
        const float det = axx * c00 + axy * c01 + axs * c02;
        const bool keep = nms && (det != 0.0f);

        float rx = 0.0f, ry = 0.0f, rs = 0.0f;
        if (keep) {
            const float inv = 1.0f / det;
            const float c11 = axx * ass - axs * axs;
            const float c12 = axy * axs - axx * ays;
            const float c22 = axx * ayy - axy * axy;
            rx = -(c00 * gx + c01 * gy + c02 * gs) * inv;
            ry = -(c01 * gx + c11 * gy + c12 * gs) * inv;
            rs = -(c02 * gx + c12 * gy + c22 * gs) * inv;
            const float big = fmaxf(fabsf(rx), fmaxf(fabsf(ry), fabsf(rs)));
            if (big > 0.7f) { rx = 0.0f; ry = 0.0f; rs = 0.0f; }
        }

        const float dyv = 0.5f * (gx * rx + gy * ry + gs * rs);
        const float y = c + dyv + (keep ? 10.0f : 0.0f);

        // coords channels: grid(d, w, h) + flipped refinement (s, y, x)
        pD[d * PLANE] = (float)d + rs;
        pW[d * PLANE] = wf + ry;
        pH[d * PLANE] = hf + rx;
        pY[d * PLANE] = y;

        if (d < Dd - 1) {
            pm1 = C[1]; pm3 = C[3]; pm4 = C[4]; pm5 = C[5]; pm7 = C[7];
            cp0 = cmc[0]; cp1 = cmc[1]; cp2 = cmc[2];
#pragma unroll
            for (int i = 0; i < 9; i++) C[i] = N[i];
#pragma unroll
            for (int i = 0; i < 3; i++) cmc[i] = cmn[i];
#pragma unroll
            for (int i = 0; i < 9; i++) N[i] = Q[i];
            COLMAX(N, cmn);
            if (d + 3 < Dd) LOADQ(d + 3, Q);  // issue next prefetch; skipped at tail
        }
    }
}

extern "C" void kernel_launch(void* const* d_in, const int* in_sizes, int n_in,
                              void* d_out, int out_size) {
    const float* x = (const float*)d_in[0];
    float* out = (float*)d_out;
    dim3 block(32, 4, 1);
    dim3 grid(Ww / 32, Hh / 4, Bb);  // (16, 128, 2)
    conv_quad_interp3d_kernel<<<grid, block>>>(x, out);
}